// round 1
// baseline (speedup 1.0000x reference)
#include <cuda_runtime.h>
#include <cuda_bf16.h>

#define B 512
#define S 1024
#define I 20
#define H 64
#define G 256  // 4*H gates

// ---- scratch (device globals; no allocation allowed) ----
__device__ int   g_tok[B * S];     // token index per (b,s), -1 if padding
__device__ int   g_len[B];         // true sequence length
__device__ float g_h[2][B * H];    // final hidden states fw/bw
__device__ float g_avblock[B * 80];

__device__ __forceinline__ float fsig(float x) {
    return 1.0f / (1.0f + __expf(-x));
}
__device__ __forceinline__ float ftanh(float x) {
    float t = __expf(2.0f * x);
    return (t - 1.0f) * (1.0f / (t + 1.0f));
}

// ============================================================
// Kernel 1: tokenize one-hot input + compute lengths
// grid: B blocks x 256 threads
// ============================================================
__global__ void k_tokenize(const float* __restrict__ input1) {
    int b = blockIdx.x;
    int tid = threadIdx.x;
    __shared__ int s_cnt[256];
    int cnt = 0;
    for (int s = tid; s < S; s += 256) {
        const float4* row = (const float4*)(input1 + ((size_t)b * S + s) * I);
        int t = -1;
        #pragma unroll
        for (int q = 0; q < 5; q++) {
            float4 v = row[q];
            if (v.x > 0.5f) t = q * 4 + 0;
            if (v.y > 0.5f) t = q * 4 + 1;
            if (v.z > 0.5f) t = q * 4 + 2;
            if (v.w > 0.5f) t = q * 4 + 3;
        }
        g_tok[b * S + s] = t;
        if (t >= 0) cnt++;
    }
    s_cnt[tid] = cnt;
    __syncthreads();
    for (int off = 128; off > 0; off >>= 1) {
        if (tid < off) s_cnt[tid] += s_cnt[tid + off];
        __syncthreads();
    }
    if (tid == 0) g_len[b] = s_cnt[0];
}

// ============================================================
// Kernel 2: LSTM, one block per (batch, direction)
// 256 threads; thread g owns gate row g (W_hh row in registers)
// ============================================================
__global__ void __launch_bounds__(256, 2)
k_lstm(const float* __restrict__ W_ih_f, const float* __restrict__ W_hh_f,
       const float* __restrict__ b_f,
       const float* __restrict__ W_ih_b, const float* __restrict__ W_hh_b,
       const float* __restrict__ b_b) {
    int b   = blockIdx.x;
    int dir = blockIdx.y;
    int g   = threadIdx.x;

    const float* W_ih = dir ? W_ih_b : W_ih_f;
    const float* W_hh = dir ? W_hh_b : W_hh_f;
    const float* bias = dir ? b_b    : b_f;

    __shared__ float s_Wih[I * G];   // transposed: [i][g]
    __shared__ float s_h[H];
    __shared__ float s_gate[G];
    __shared__ int   s_tok[S];

    // stage W_ih transposed (conflict-free gather later)
    for (int idx = g; idx < G * I; idx += 256) {
        int gg = idx / I, ii = idx % I;
        s_Wih[ii * G + gg] = W_ih[idx];
    }
    // stage tokens
    for (int s = g; s < S; s += 256) s_tok[s] = g_tok[b * S + s];
    // W_hh row -> registers
    float wreg[H];
    {
        const float4* w4 = (const float4*)(W_hh + g * H);
        #pragma unroll
        for (int q = 0; q < H / 4; q++) {
            float4 v = w4[q];
            wreg[q * 4 + 0] = v.x; wreg[q * 4 + 1] = v.y;
            wreg[q * 4 + 2] = v.z; wreg[q * 4 + 3] = v.w;
        }
    }
    float breg = bias[g];
    float c = 0.0f;
    if (g < H) s_h[g] = 0.0f;
    __syncthreads();

    for (int t = 0; t < S; t++) {
        int s   = dir ? (S - 1 - t) : t;
        int tok = s_tok[s];
        float gv = breg;
        if (tok >= 0) gv += s_Wih[tok * G + g];
        #pragma unroll
        for (int j0 = 0; j0 < H; j0 += 4) {
            float4 h4 = *(const float4*)(s_h + j0);
            gv = fmaf(wreg[j0 + 0], h4.x, gv);
            gv = fmaf(wreg[j0 + 1], h4.y, gv);
            gv = fmaf(wreg[j0 + 2], h4.z, gv);
            gv = fmaf(wreg[j0 + 3], h4.w, gv);
        }
        s_gate[g] = gv;
        __syncthreads();
        if (g < H) {
            float ig = s_gate[g];
            float fg = s_gate[H + g];
            float gg = s_gate[2 * H + g];
            float og = s_gate[3 * H + g];
            c = fsig(fg) * c + fsig(ig) * ftanh(gg);
            s_h[g] = fsig(og) * ftanh(c);
        }
        __syncthreads();
    }

    if (g < H) g_h[dir][b * H + g] = s_h[g];
}

// ============================================================
// Kernel 3: conv1 (token gather) + torch-reshape + ragged 4-bin mean
// grid: B blocks x 128 threads
// ============================================================
__global__ void k_avblock(const float* __restrict__ conv1_w) {
    int b = blockIdx.x;
    int tid = threadIdx.x;
    __shared__ int   s_tok[S];
    __shared__ float s_w[I * I];
    for (int s = tid; s < S; s += 128) s_tok[s] = g_tok[b * S + s];
    for (int i = tid; i < I * I; i += 128) s_w[i] = conv1_w[i];
    __syncthreads();

    int bw = g_len[b] / 4;
    if (tid < 80) {
        int k = tid / I, cc = tid % I;
        float sum = 0.0f;
        for (int s = k * bw; s < (k + 1) * bw; s++) {
            // c1 computed as [20,S] per batch, torch-reshaped to [S,20]:
            int flat = s * I + cc;
            int ch = flat >> 10;       // flat / S  (S=1024)
            int p  = flat & (S - 1);   // flat % S
            int tk = s_tok[p];
            if (tk >= 0) sum += s_w[ch * I + tk];
        }
        g_avblock[b * 80 + tid] = sum / (float)bw;
    }
}

// ============================================================
// Kernel 4: conv2+relu, concat, fc1, fc2, softmax
// grid: B blocks x 128 threads
// ============================================================
__global__ void k_head(const float* __restrict__ conv2_w,
                       const float* __restrict__ conv2_b,
                       const float* __restrict__ fc1_w,
                       const float* __restrict__ fc1_b,
                       const float* __restrict__ fc2_w,
                       const float* __restrict__ fc2_b,
                       float* __restrict__ out) {
    int b = blockIdx.x;
    int tid = threadIdx.x;
    __shared__ float s_m[228];
    __shared__ float s_av[80];
    __shared__ float s_f[64];

    if (tid < 64)            s_m[tid]      = g_h[0][b * H + tid];
    else if (tid < 128)      s_m[tid]      = g_h[1][b * H + tid - 64];
    if (tid < 80)            s_av[tid]     = g_avblock[b * 80 + tid];
    __syncthreads();

    if (tid < 100) {
        float acc = conv2_b[tid];
        const float* w = conv2_w + tid * 80;
        #pragma unroll 8
        for (int j = 0; j < 80; j++) acc = fmaf(s_av[j], w[j], acc);
        s_m[128 + tid] = fmaxf(acc, 0.0f);
    }
    __syncthreads();

    if (tid < 64) {
        float acc = fc1_b[tid];
        const float* w = fc1_w + tid * 228;
        for (int j = 0; j < 228; j++) acc = fmaf(s_m[j], w[j], acc);
        s_f[tid] = acc;
    }
    __syncthreads();

    if (tid == 0) {
        float a0 = fc2_b[0], a1 = fc2_b[1];
        #pragma unroll 8
        for (int j = 0; j < 64; j++) {
            a0 = fmaf(s_f[j], fc2_w[j], a0);
            a1 = fmaf(s_f[j], fc2_w[64 + j], a1);
        }
        float m  = fmaxf(a0, a1);
        float e0 = __expf(a0 - m), e1 = __expf(a1 - m);
        float inv = 1.0f / (e0 + e1);
        out[b * 2 + 0] = e0 * inv;
        out[b * 2 + 1] = e1 * inv;
    }
}

extern "C" void kernel_launch(void* const* d_in, const int* in_sizes, int n_in,
                              void* d_out, int out_size) {
    const float* input1  = (const float*)d_in[0];
    const float* W_ih_f  = (const float*)d_in[1];
    const float* W_hh_f  = (const float*)d_in[2];
    const float* b_f     = (const float*)d_in[3];
    const float* W_ih_b  = (const float*)d_in[4];
    const float* W_hh_b  = (const float*)d_in[5];
    const float* b_b     = (const float*)d_in[6];
    const float* conv1_w = (const float*)d_in[7];
    const float* conv2_w = (const float*)d_in[8];
    const float* conv2_b = (const float*)d_in[9];
    const float* fc1_w   = (const float*)d_in[10];
    const float* fc1_b   = (const float*)d_in[11];
    const float* fc2_w   = (const float*)d_in[12];
    const float* fc2_b   = (const float*)d_in[13];
    float* out = (float*)d_out;

    k_tokenize<<<B, 256>>>(input1);
    dim3 lgrid(B, 2);
    k_lstm<<<lgrid, 256>>>(W_ih_f, W_hh_f, b_f, W_ih_b, W_hh_b, b_b);
    k_avblock<<<B, 128>>>(conv1_w);
    k_head<<<B, 128>>>(conv2_w, conv2_b, fc1_w, fc1_b, fc2_w, fc2_b, out);
}